// round 2
// baseline (speedup 1.0000x reference)
#include <cuda_runtime.h>

// DynamicWeightAttention: fused LN(concat(dyn,static)) -> 32x64 GEMV -> tanh
// -> 64->1 dot -> softmax over H=16 consecutive rows.
// Shapes: B_T=1024, N=256, H=16, Pd=Ps=16 (C=32), HID=64. Rows = 4,194,304.

#define ROWS_PER_BLOCK 256
#define C_FEAT 32
#define PD 16
#define HID 64
#define XS_STRIDE 36   // padded row stride in floats (conflict-free, 16B-aligned)

typedef unsigned long long u64;

__device__ __forceinline__ u64 pk2(float a, float b) {
    u64 r; asm("mov.b64 %0, {%1, %2};" : "=l"(r) : "f"(a), "f"(b)); return r;
}
__device__ __forceinline__ void upk2(u64 v, float& a, float& b) {
    asm("mov.b64 {%0, %1}, %2;" : "=f"(a), "=f"(b) : "l"(v));
}
__device__ __forceinline__ u64 fma2(u64 a, u64 b, u64 c) {
    u64 d; asm("fma.rn.f32x2 %0, %1, %2, %3;" : "=l"(d) : "l"(a), "l"(b), "l"(c)); return d;
}
__device__ __forceinline__ float tanha(float x) {
    float r; asm("tanh.approx.f32 %0, %1;" : "=f"(r) : "f"(x)); return r;
}

__global__ __launch_bounds__(256, 2)
void dwa_kernel(const float* __restrict__ dyn, const float* __restrict__ stat,
                const float* __restrict__ gamma, const float* __restrict__ beta,
                const float* __restrict__ w1, const float* __restrict__ b1,
                const float* __restrict__ w2, const float* __restrict__ b2,
                float* __restrict__ out)
{
    __shared__ __align__(16) float xs[ROWS_PER_BLOCK * XS_STRIDE];   // 36 KB
    __shared__ __align__(16) float w1s[C_FEAT * HID];                // 8 KB
    __shared__ __align__(16) float b1s[HID];
    __shared__ __align__(16) float w2s[HID];
    __shared__ float gs[C_FEAT], bs[C_FEAT];
    __shared__ float b2s_;

    const int tid = threadIdx.x;
    const long base = (long)blockIdx.x * ROWS_PER_BLOCK;

    // ---- Stage dynamic features: 256 rows x 16 floats = 1024 float4, coalesced
    {
        const float4* dyn4 = (const float4*)dyn + base * 4;  // base*16 floats / 4
        float4* xs4 = (float4*)xs;
        #pragma unroll
        for (int i = tid; i < ROWS_PER_BLOCK * 4; i += 256) {
            int r = i >> 2, c4 = i & 3;
            xs4[r * 9 + c4] = dyn4[i];          // 9 float4 = 36-float stride
        }
    }
    // ---- Stage static features: row r uses static row (r mod N*H=4096);
    //      base is 256-aligned and 4096 % 256 == 0 -> contiguous slice, no wrap.
    {
        const int sbase = (int)(base & 4095);
        const float4* st4 = (const float4*)stat + (long)sbase * 4;
        float4* xs4 = (float4*)xs;
        #pragma unroll
        for (int i = tid; i < ROWS_PER_BLOCK * 4; i += 256) {
            int r = i >> 2, c4 = i & 3;
            xs4[r * 9 + 4 + c4] = st4[i];
        }
    }
    // ---- Stage w1 (32x64 row-major = 512 float4)
    {
        const float4* w14 = (const float4*)w1;
        float4* w1s4 = (float4*)w1s;
        #pragma unroll
        for (int i = tid; i < 512; i += 256) w1s4[i] = w14[i];
    }
    // ---- Small params
    if (tid < C_FEAT)                { gs[tid] = gamma[tid]; bs[tid] = beta[tid]; }
    else if (tid < C_FEAT + HID)     { b1s[tid - C_FEAT] = b1[tid - C_FEAT]; }
    else if (tid < C_FEAT + 2*HID)   { w2s[tid - C_FEAT - HID] = w2[tid - C_FEAT - HID]; }
    else if (tid == C_FEAT + 2*HID)  { b2s_ = b2[0]; }
    __syncthreads();

    // ---- Load my row into registers (8x LDS.128, conflict-free w/ stride 36)
    float x[C_FEAT];
    {
        const float4* myx = (const float4*)(xs + tid * XS_STRIDE);
        #pragma unroll
        for (int k = 0; k < 8; k++) {
            float4 v = myx[k];
            x[4*k] = v.x; x[4*k+1] = v.y; x[4*k+2] = v.z; x[4*k+3] = v.w;
        }
    }

    // ---- LayerNorm (biased var, eps=1e-4)
    float s = 0.f, ss = 0.f;
    #pragma unroll
    for (int c = 0; c < C_FEAT; c++) { s += x[c]; ss += x[c] * x[c]; }
    const float mean = s * (1.0f / C_FEAT);
    const float var  = ss * (1.0f / C_FEAT) - mean * mean;
    const float rstd = rsqrtf(var + 1e-4f);
    #pragma unroll
    for (int c = 0; c < C_FEAT; c++) {
        float sc = rstd * gs[c];
        x[c] = (x[c] - mean) * sc + bs[c];
    }

    // ---- GEMV 32x64 with packed f32x2 (pairs of output dims).
    // w1s viewed as ulonglong2: each LDS.128 yields two packed (d,d+1) weight pairs.
    u64 acc[HID / 2];
    {
        const ulonglong2* b1u = (const ulonglong2*)b1s;
        #pragma unroll
        for (int j = 0; j < 16; j++) { ulonglong2 v = b1u[j]; acc[2*j] = v.x; acc[2*j+1] = v.y; }
    }
    {
        const ulonglong2* w1u = (const ulonglong2*)w1s;
        #pragma unroll
        for (int c = 0; c < C_FEAT; c++) {
            u64 xc = pk2(x[c], x[c]);
            #pragma unroll
            for (int j = 0; j < 16; j++) {
                ulonglong2 w = w1u[c * 16 + j];     // broadcast LDS.128
                acc[2*j]   = fma2(xc, w.x, acc[2*j]);
                acc[2*j+1] = fma2(xc, w.y, acc[2*j+1]);
            }
        }
    }

    // ---- tanh + second layer (64 -> 1)
    float score = b2s_;
    #pragma unroll
    for (int p = 0; p < HID / 2; p++) {
        float a, b; upk2(acc[p], a, b);
        score += tanha(a) * w2s[2*p] + tanha(b) * w2s[2*p + 1];
    }

    // ---- Softmax over H=16 consecutive rows (lanes grouped by 16 within warp)
    float m = score;
    #pragma unroll
    for (int o = 8; o; o >>= 1) m = fmaxf(m, __shfl_xor_sync(0xffffffffu, m, o, 16));
    float e = __expf(score - m);
    float sum = e;
    #pragma unroll
    for (int o = 8; o; o >>= 1) sum += __shfl_xor_sync(0xffffffffu, sum, o, 16);

    out[base + tid] = e * (1.0f / sum);
}

extern "C" void kernel_launch(void* const* d_in, const int* in_sizes, int n_in,
                              void* d_out, int out_size) {
    const float* dyn   = (const float*)d_in[0];
    const float* stat  = (const float*)d_in[1];
    const float* gamma = (const float*)d_in[2];
    const float* beta  = (const float*)d_in[3];
    const float* w1    = (const float*)d_in[4];
    const float* b1    = (const float*)d_in[5];
    const float* w2    = (const float*)d_in[6];
    const float* b2    = (const float*)d_in[7];
    float* out = (float*)d_out;

    const long nrows = (long)in_sizes[0] / PD;            // 4,194,304
    const int  nblocks = (int)(nrows / ROWS_PER_BLOCK);   // 16,384

    dwa_kernel<<<nblocks, 256>>>(dyn, stat, gamma, beta, w1, b1, w2, b2, out);
}

// round 8
// speedup vs baseline: 2.1307x; 2.1307x over previous
#include <cuda_runtime.h>
#include <cstdint>

// DynamicWeightAttention via mma.sync tf32 (sm_80-baseline PTX; tcgen05 needs
// the 'a' target feature which this build's PTX stage doesn't have).
//
// Transposed GEMM: D^T[64, M] = W'^T[64,32] x X^T[32, M]
//   A = W'^T (weights) -> registers, loaded once per block, reused over tiles.
//   B = X^T   (activations) -> smem fragments, XOR-swizzled.
// LayerNorm folds into the epilogue:
//   h_d = (dot_d - mean*u_d)*rstd + v_d;  score = sum_d tanh(h_d)*w2_d + b2;
//   softmax over H=16 consecutive rows.
// M = 4,194,304 rows; 128 rows/tile; 32768 tiles; grid 2048 x 16 tiles each.
// Staging: 256 threads, HALF a row per thread (t>>1 = row, t&1 = half).

#define C_FEAT 32
#define HID    64
#define TILE_M 128
#define GRID_B 2048

// ---- prep outputs (device globals; no allocation) ----
__device__ float g_W[HID * C_FEAT];   // [d][k] = tf32(gamma[k]*w1[k][d])
__device__ float g_u[HID];            // u_d = sum_k g_W[d][k]   (rounded weights)
__device__ float g_v[HID];            // v_d = sum_k beta[k]*w1[k][d] + b1[d]
__device__ float g_w2[HID];
__device__ float g_b2;

__device__ __forceinline__ uint32_t tf32r(float x) {
    uint32_t r; asm("cvt.rna.tf32.f32 %0, %1;" : "=r"(r) : "f"(x)); return r;
}
__device__ __forceinline__ float tanha(float x) {
    float r; asm("tanh.approx.f32 %0, %1;" : "=f"(r) : "f"(x)); return r;
}
__device__ __forceinline__ void mma8(float& d0, float& d1, float& d2, float& d3,
                                     uint32_t a0, uint32_t a1, uint32_t a2, uint32_t a3,
                                     uint32_t b0, uint32_t b1) {
    asm("mma.sync.aligned.m16n8k8.row.col.f32.tf32.tf32.f32 "
        "{%0,%1,%2,%3}, {%4,%5,%6,%7}, {%8,%9}, {%0,%1,%2,%3};"
        : "+f"(d0), "+f"(d1), "+f"(d2), "+f"(d3)
        : "r"(a0), "r"(a1), "r"(a2), "r"(a3), "r"(b0), "r"(b1));
}

__global__ void prep_kernel(const float* __restrict__ gamma, const float* __restrict__ beta,
                            const float* __restrict__ w1,    const float* __restrict__ b1,
                            const float* __restrict__ w2,    const float* __restrict__ b2) {
    int d = threadIdx.x;
    if (d >= HID) return;
    float u = 0.f, v = 0.f;
    for (int k = 0; k < C_FEAT; k++) {
        float wp = __uint_as_float(tf32r(gamma[k] * w1[k * HID + d]));
        g_W[d * C_FEAT + k] = wp;
        u += wp;
        v += beta[k] * w1[k * HID + d];
    }
    g_u[d] = u;
    g_v[d] = v + b1[d];
    g_w2[d] = w2[d];
    if (d == 0) g_b2 = b2[0];
}

__global__ __launch_bounds__(256, 2)
void dwa_kernel(const float* __restrict__ dyn, const float* __restrict__ stat,
                float* __restrict__ out, int tiles_per_block) {
    // X tile: 128 rows x 32 tf32 words, XOR-swizzled col' = col ^ 4*(row&7)
    __shared__ uint32_t xs[TILE_M * C_FEAT];          // 16 KB
    __shared__ float means[TILE_M], rstds[TILE_M];    // 1 KB
    __shared__ float us[HID], vs[HID], w2s[HID];
    __shared__ float b2s;

    const int tid  = threadIdx.x;
    const int lane = tid & 31;
    const int wid  = tid >> 5;
    const int g    = lane >> 2;     // groupID
    const int c    = lane & 3;      // threadID_in_group
    const int lrow = tid >> 1;      // local row this thread stages (0..127)
    const int half = tid & 1;       // which 8-col slice of dyn AND of stat

    // ---- one-time staging of epilogue params ----
    if (tid < HID) { us[tid] = g_u[tid]; vs[tid] = g_v[tid]; w2s[tid] = g_w2[tid]; }
    if (tid == 0)  b2s = g_b2;

    // ---- A fragments (weights) in registers, loaded once per block ----
    // A = W'^T: m-dim = hidden d (4 tiles of 16), k-dim = feature (4 steps of 8)
    // a0: d=16mt+g, k=8ks+c ; a1: d+8 ; a2: k+4 ; a3: both
    uint32_t afr[4][4][4];
    #pragma unroll
    for (int mt = 0; mt < 4; mt++) {
        #pragma unroll
        for (int ks = 0; ks < 4; ks++) {
            int d0 = mt * 16 + g, k0 = ks * 8 + c;
            afr[mt][ks][0] = __float_as_uint(g_W[d0 * 32 + k0]);
            afr[mt][ks][1] = __float_as_uint(g_W[(d0 + 8) * 32 + k0]);
            afr[mt][ks][2] = __float_as_uint(g_W[d0 * 32 + k0 + 4]);
            afr[mt][ks][3] = __float_as_uint(g_W[(d0 + 8) * 32 + k0 + 4]);
        }
    }

    for (int it = 0; it < tiles_per_block; it++) {
        const long tile  = (long)blockIdx.x * tiles_per_block + it;
        const long rbase = tile * TILE_M;
        const long row   = rbase + lrow;

        // ---- stage half a row into registers BEFORE the barrier ----
        // thread 'half' h loads dyn cols 8h..8h+7 and stat cols 8h..8h+7
        // (4 float4 loads, lane-adjacent addresses contiguous -> coalesced)
        uint32_t xw[16];
        float s = 0.f, ss = 0.f;
        {
            const float4* d4 = (const float4*)dyn + row * 4 + half * 2;
            const float4* s4 = (const float4*)stat + (long)(row & 4095) * 4 + half * 2;
            #pragma unroll
            for (int k = 0; k < 2; k++) {
                float4 v = d4[k];
                s += v.x + v.y + v.z + v.w;
                ss += v.x*v.x + v.y*v.y + v.z*v.z + v.w*v.w;
                xw[4*k] = tf32r(v.x); xw[4*k+1] = tf32r(v.y);
                xw[4*k+2] = tf32r(v.z); xw[4*k+3] = tf32r(v.w);
            }
            #pragma unroll
            for (int k = 0; k < 2; k++) {
                float4 v = s4[k];
                s += v.x + v.y + v.z + v.w;
                ss += v.x*v.x + v.y*v.y + v.z*v.z + v.w*v.w;
                xw[8+4*k] = tf32r(v.x); xw[8+4*k+1] = tf32r(v.y);
                xw[8+4*k+2] = tf32r(v.z); xw[8+4*k+3] = tf32r(v.w);
            }
        }
        // combine LN partials with partner lane (same row, other half)
        s  += __shfl_xor_sync(0xffffffffu, s, 1);
        ss += __shfl_xor_sync(0xffffffffu, ss, 1);
        const float mean = s * (1.0f / C_FEAT);
        const float var  = ss * (1.0f / C_FEAT) - mean * mean;
        const float rstd = rsqrtf(var + 1e-4f);

        __syncthreads();   // previous iteration's readers done with xs/means

        means[lrow] = mean;    // duplicate write by both halves: same value
        rstds[lrow] = rstd;
        // Fused-row chunk layout (float4 index jj): jj 0-3 = dyn cols 0-15,
        // jj 4-7 = stat cols 16-31. This thread's chunks:
        //   dyn  cols 8h..8h+7  -> jj = 2*half + j     (j = 0,1)
        //   stat cols 8h..8h+7  -> jj = 4 + 2*half + j (j = 0,1)
        // Swizzled store: jj ^ (lrow & 7).
        {
            uint4* xs4 = (uint4*)xs;
            #pragma unroll
            for (int j = 0; j < 2; j++) {
                uint4 v;
                v.x = xw[4*j];   v.y = xw[4*j+1];
                v.z = xw[4*j+2]; v.w = xw[4*j+3];
                int jj = 2 * half + j;
                xs4[lrow * 8 + (jj ^ (lrow & 7))] = v;
            }
            #pragma unroll
            for (int j = 0; j < 2; j++) {
                uint4 v;
                v.x = xw[8+4*j];   v.y = xw[8+4*j+1];
                v.z = xw[8+4*j+2]; v.w = xw[8+4*j+3];
                int jj = 4 + 2 * half + j;
                xs4[lrow * 8 + (jj ^ (lrow & 7))] = v;
            }
        }
        __syncthreads();

        // ---- MMA: warp handles 16 rows (cols of D^T) = one softmax group ----
        float acc[4][2][4];
        #pragma unroll
        for (int mt = 0; mt < 4; mt++)
            #pragma unroll
            for (int nt = 0; nt < 2; nt++)
                #pragma unroll
                for (int q = 0; q < 4; q++) acc[mt][nt][q] = 0.f;

        #pragma unroll
        for (int ks = 0; ks < 4; ks++) {
            uint32_t b[2][2];
            #pragma unroll
            for (int nt = 0; nt < 2; nt++) {
                int brow = wid * 16 + nt * 8 + g;       // b: k=8ks+c(+4), n-col=brow
                int col0 = ks * 8 + c;
                b[nt][0] = xs[brow * 32 + ((col0)     ^ (4 * (g & 7)))];
                b[nt][1] = xs[brow * 32 + ((col0 + 4) ^ (4 * (g & 7)))];
            }
            #pragma unroll
            for (int mt = 0; mt < 4; mt++)
                #pragma unroll
                for (int nt = 0; nt < 2; nt++)
                    mma8(acc[mt][nt][0], acc[mt][nt][1], acc[mt][nt][2], acc[mt][nt][3],
                         afr[mt][ks][0], afr[mt][ks][1], afr[mt][ks][2], afr[mt][ks][3],
                         b[nt][0], b[nt][1]);
        }

        // ---- epilogue: thread holds d in {16mt+g, +8}, rows {8nt+2c, +1} ----
        float sc[2][2];
        float mrow[2][2], rrow[2][2];
        #pragma unroll
        for (int nt = 0; nt < 2; nt++)
            #pragma unroll
            for (int i = 0; i < 2; i++) {
                int r = wid * 16 + nt * 8 + 2 * c + i;
                mrow[nt][i] = means[r]; rrow[nt][i] = rstds[r];
                sc[nt][i] = 0.f;
            }
        #pragma unroll
        for (int mt = 0; mt < 4; mt++) {
            #pragma unroll
            for (int hh = 0; hh < 2; hh++) {
                int d = mt * 16 + g + 8 * hh;
                float ud = us[d], vd = vs[d], wd = w2s[d];
                #pragma unroll
                for (int nt = 0; nt < 2; nt++) {
                    #pragma unroll
                    for (int i = 0; i < 2; i++) {
                        float t1 = fmaf(-mrow[nt][i], ud, acc[mt][nt][2*hh + i]);
                        float h  = fmaf(t1, rrow[nt][i], vd);
                        sc[nt][i] = fmaf(tanha(h), wd, sc[nt][i]);
                    }
                }
            }
        }
        // reduce partial scores over g-lanes (offsets 4,8,16 preserve c)
        #pragma unroll
        for (int o = 4; o <= 16; o <<= 1) {
            #pragma unroll
            for (int nt = 0; nt < 2; nt++)
                #pragma unroll
                for (int i = 0; i < 2; i++)
                    sc[nt][i] += __shfl_xor_sync(0xffffffffu, sc[nt][i], o);
        }
        const float b2v = b2s;
        #pragma unroll
        for (int nt = 0; nt < 2; nt++)
            #pragma unroll
            for (int i = 0; i < 2; i++) sc[nt][i] += b2v;

        // softmax over the warp's 16 rows (4 per lane, duplicated over g)
        float m = fmaxf(fmaxf(sc[0][0], sc[0][1]), fmaxf(sc[1][0], sc[1][1]));
        m = fmaxf(m, __shfl_xor_sync(0xffffffffu, m, 1));
        m = fmaxf(m, __shfl_xor_sync(0xffffffffu, m, 2));
        float e[2][2], esum = 0.f;
        #pragma unroll
        for (int nt = 0; nt < 2; nt++)
            #pragma unroll
            for (int i = 0; i < 2; i++) { e[nt][i] = __expf(sc[nt][i] - m); esum += e[nt][i]; }
        esum += __shfl_xor_sync(0xffffffffu, esum, 1);
        esum += __shfl_xor_sync(0xffffffffu, esum, 2);
        const float inv = 1.0f / esum;

        if (g == 0) {
            #pragma unroll
            for (int nt = 0; nt < 2; nt++)
                #pragma unroll
                for (int i = 0; i < 2; i++)
                    out[rbase + wid * 16 + nt * 8 + 2 * c + i] = e[nt][i] * inv;
        }
    }
}

extern "C" void kernel_launch(void* const* d_in, const int* in_sizes, int n_in,
                              void* d_out, int out_size) {
    const float* dyn   = (const float*)d_in[0];
    const float* stat  = (const float*)d_in[1];
    const float* gamma = (const float*)d_in[2];
    const float* beta  = (const float*)d_in[3];
    const float* w1    = (const float*)d_in[4];
    const float* b1    = (const float*)d_in[5];
    const float* w2    = (const float*)d_in[6];
    const float* b2    = (const float*)d_in[7];
    float* out = (float*)d_out;

    const long nrows = (long)in_sizes[0] / 16;      // 4,194,304
    const long tiles = nrows / TILE_M;              // 32,768
    const int  tpb   = (int)(tiles / GRID_B);       // 16

    prep_kernel<<<1, 64>>>(gamma, beta, w1, b1, w2, b2);
    dwa_kernel<<<GRID_B, 256>>>(dyn, stat, out, tpb);
}

// round 9
// speedup vs baseline: 2.2777x; 1.0690x over previous
#include <cuda_runtime.h>
#include <cstdint>

// DynamicWeightAttention via mma.sync tf32, double-buffered, k-reordered smem.
// D^T[64,M] = W'^T[64,32] x X^T[32,M]; LN folded into epilogue; softmax over 16.
// X smem layout: word k of a row stored at p = (k&3)*8 + (k>>3)*2 + ((k>>2)&1),
// so each thread's b-fragment (8ks+c, 8ks+c+4; ks=0..3) is 8 contiguous words
// -> 2x LDS.128 per row. Row stride 36 words (conflict-free).

#define C_FEAT 32
#define HID    64
#define TILE_M 128
#define GRID_B 2048
#define XROW   36                 // padded words per row
#define XBUF   (TILE_M * XROW)    // words per buffer

// ---- prep outputs (device globals; no allocation) ----
__device__ float  g_W[HID * C_FEAT];  // [d][k] = tf32(gamma[k]*w1[k][d])
__device__ float4 g_p4[HID];          // {u_d, v_d, w2_d, 0}
__device__ float  g_b2;

__device__ __forceinline__ uint32_t tf32r(float x) {
    uint32_t r; asm("cvt.rna.tf32.f32 %0, %1;" : "=r"(r) : "f"(x)); return r;
}
__device__ __forceinline__ float tanha(float x) {
    float r; asm("tanh.approx.f32 %0, %1;" : "=f"(r) : "f"(x)); return r;
}
__device__ __forceinline__ void mma8(float& d0, float& d1, float& d2, float& d3,
                                     uint32_t a0, uint32_t a1, uint32_t a2, uint32_t a3,
                                     uint32_t b0, uint32_t b1) {
    asm("mma.sync.aligned.m16n8k8.row.col.f32.tf32.tf32.f32 "
        "{%0,%1,%2,%3}, {%4,%5,%6,%7}, {%8,%9}, {%0,%1,%2,%3};"
        : "+f"(d0), "+f"(d1), "+f"(d2), "+f"(d3)
        : "r"(a0), "r"(a1), "r"(a2), "r"(a3), "r"(b0), "r"(b1));
}

__global__ void prep_kernel(const float* __restrict__ gamma, const float* __restrict__ beta,
                            const float* __restrict__ w1,    const float* __restrict__ b1,
                            const float* __restrict__ w2,    const float* __restrict__ b2) {
    int d = threadIdx.x;
    if (d >= HID) return;
    float u = 0.f, v = 0.f;
    for (int k = 0; k < C_FEAT; k++) {
        float wp = __uint_as_float(tf32r(gamma[k] * w1[k * HID + d]));
        g_W[d * C_FEAT + k] = wp;
        u += wp;
        v += beta[k] * w1[k * HID + d];
    }
    g_p4[d] = make_float4(u, v + b1[d], w2[d], 0.f);
    if (d == 0) g_b2 = b2[0];
}

__global__ __launch_bounds__(256, 2)
void dwa_kernel(const float* __restrict__ dyn, const float* __restrict__ stat,
                float* __restrict__ out, int tiles_per_block) {
    __shared__ uint32_t xs[2 * XBUF];                 // 36 KB (double buffer)
    __shared__ __align__(16) float4 p4s[HID];         // 1 KB
    __shared__ float b2s;

    const int tid  = threadIdx.x;
    const int lane = tid & 31;
    const int wid  = tid >> 5;
    const int g    = lane >> 2;     // groupID
    const int c    = lane & 3;      // threadID_in_group
    const int lrow = tid >> 1;      // local row this thread stages (0..127)
    const int half = tid & 1;       // 8-col slice of dyn AND of stat

    if (tid < HID) p4s[tid] = g_p4[tid];
    if (tid == 0)  b2s = g_b2;

    // ---- A fragments (weights) in registers, loaded once per block ----
    // a0: d=16mt+g, k=8ks+c ; a1: d+8 ; a2: k+4 ; a3: both
    uint32_t afr[4][4][4];
    #pragma unroll
    for (int mt = 0; mt < 4; mt++) {
        #pragma unroll
        for (int ks = 0; ks < 4; ks++) {
            int d0 = mt * 16 + g, k0 = ks * 8 + c;
            afr[mt][ks][0] = __float_as_uint(g_W[d0 * 32 + k0]);
            afr[mt][ks][1] = __float_as_uint(g_W[(d0 + 8) * 32 + k0]);
            afr[mt][ks][2] = __float_as_uint(g_W[d0 * 32 + k0 + 4]);
            afr[mt][ks][3] = __float_as_uint(g_W[(d0 + 8) * 32 + k0 + 4]);
        }
    }
    __syncthreads();   // p4s/b2s visible

    for (int it = 0; it < tiles_per_block; it++) {
        const long tile  = (long)blockIdx.x * tiles_per_block + it;
        const long rbase = tile * TILE_M;
        const long row   = rbase + lrow;
        uint32_t* xb = xs + (it & 1) * XBUF;

        // ---- stage half a row into registers (before the barrier) ----
        // thread 'half' h: dyn cols 8h..8h+7 (k=8h+j) and stat cols (k=16+8h+j)
        uint32_t xw[16];
        float s = 0.f, ss = 0.f;
        {
            const float4* d4 = (const float4*)dyn + row * 4 + half * 2;
            const float4* s4 = (const float4*)stat + (long)(row & 4095) * 4 + half * 2;
            #pragma unroll
            for (int k = 0; k < 2; k++) {
                float4 v = d4[k];
                s += v.x + v.y + v.z + v.w;
                ss += v.x*v.x + v.y*v.y + v.z*v.z + v.w*v.w;
                xw[4*k] = tf32r(v.x); xw[4*k+1] = tf32r(v.y);
                xw[4*k+2] = tf32r(v.z); xw[4*k+3] = tf32r(v.w);
            }
            #pragma unroll
            for (int k = 0; k < 2; k++) {
                float4 v = s4[k];
                s += v.x + v.y + v.z + v.w;
                ss += v.x*v.x + v.y*v.y + v.z*v.z + v.w*v.w;
                xw[8+4*k] = tf32r(v.x); xw[8+4*k+1] = tf32r(v.y);
                xw[8+4*k+2] = tf32r(v.z); xw[8+4*k+3] = tf32r(v.w);
            }
        }
        // combine LN partials with partner lane (same row, other half)
        s  += __shfl_xor_sync(0xffffffffu, s, 1);
        ss += __shfl_xor_sync(0xffffffffu, ss, 1);
        const float mean = s * (1.0f / C_FEAT);
        const float var  = ss * (1.0f / C_FEAT) - mean * mean;
        const float rstd = rsqrtf(var + 1e-4f);

        // ---- k-reordered stores: word k -> p = (k&3)*8 + (k>>3)*2 + ((k>>2)&1)
        // dyn  (ks=half):   pair {xw[j], xw[j+4]}   at p = j*8 + 2*half      (j=0..3 is c)
        // stat (ks=half+2): pair {xw[8+j], xw[12+j]} at p = j*8 + 4 + 2*half
        {
            uint32_t* xr = xb + lrow * XROW;
            #pragma unroll
            for (int j = 0; j < 4; j++) {
                *(uint2*)(xr + j * 8 + 2 * half)     = make_uint2(xw[j],     xw[j + 4]);
                *(uint2*)(xr + j * 8 + 4 + 2 * half) = make_uint2(xw[8 + j], xw[12 + j]);
            }
        }
        __syncthreads();   // single barrier per tile (double buffer proof in header)

        // ---- b fragments: 2x LDS.128 per nt-row ----
        // reg order q = 2ks + b2: b0(ks)=q[2ks], b1(ks)=q[2ks+1]
        uint4 blo[2], bhi[2];
        #pragma unroll
        for (int nt = 0; nt < 2; nt++) {
            int brow = wid * 16 + nt * 8 + g;
            const uint4* q = (const uint4*)(xb + brow * XROW + c * 8);
            blo[nt] = q[0]; bhi[nt] = q[1];
        }

        float acc[4][2][4];
        #pragma unroll
        for (int mt = 0; mt < 4; mt++)
            #pragma unroll
            for (int nt = 0; nt < 2; nt++)
                #pragma unroll
                for (int q = 0; q < 4; q++) acc[mt][nt][q] = 0.f;

        #pragma unroll
        for (int ks = 0; ks < 4; ks++) {
            #pragma unroll
            for (int nt = 0; nt < 2; nt++) {
                uint32_t b0 = (ks == 0) ? blo[nt].x : (ks == 1) ? blo[nt].z
                             : (ks == 2) ? bhi[nt].x : bhi[nt].z;
                uint32_t b1 = (ks == 0) ? blo[nt].y : (ks == 1) ? blo[nt].w
                             : (ks == 2) ? bhi[nt].y : bhi[nt].w;
                #pragma unroll
                for (int mt = 0; mt < 4; mt++)
                    mma8(acc[mt][nt][0], acc[mt][nt][1], acc[mt][nt][2], acc[mt][nt][3],
                         afr[mt][ks][0], afr[mt][ks][1], afr[mt][ks][2], afr[mt][ks][3],
                         b0, b1);
            }
        }

        // ---- epilogue: thread holds d in {16mt+g, +8}, rows {8nt+2c, +1} ----
        // mean/rstd of local row lr live in lane 2*lr of this same warp
        float sc[2][2], mrow[2][2], rrow[2][2];
        #pragma unroll
        for (int nt = 0; nt < 2; nt++)
            #pragma unroll
            for (int i = 0; i < 2; i++) {
                int src = (nt * 8 + 2 * c + i) * 2;
                mrow[nt][i] = __shfl_sync(0xffffffffu, mean, src);
                rrow[nt][i] = __shfl_sync(0xffffffffu, rstd, src);
                sc[nt][i] = 0.f;
            }
        #pragma unroll
        for (int mt = 0; mt < 4; mt++) {
            #pragma unroll
            for (int hh = 0; hh < 2; hh++) {
                int d = mt * 16 + g + 8 * hh;
                float4 p = p4s[d];          // {u, v, w2}
                #pragma unroll
                for (int nt = 0; nt < 2; nt++) {
                    #pragma unroll
                    for (int i = 0; i < 2; i++) {
                        float t1 = fmaf(-mrow[nt][i], p.x, acc[mt][nt][2*hh + i]);
                        float h  = fmaf(t1, rrow[nt][i], p.y);
                        sc[nt][i] = fmaf(tanha(h), p.z, sc[nt][i]);
                    }
                }
            }
        }
        // reduce partial scores over g-lanes (offsets 4,8,16 preserve c)
        #pragma unroll
        for (int o = 4; o <= 16; o <<= 1) {
            #pragma unroll
            for (int nt = 0; nt < 2; nt++)
                #pragma unroll
                for (int i = 0; i < 2; i++)
                    sc[nt][i] += __shfl_xor_sync(0xffffffffu, sc[nt][i], o);
        }
        const float b2v = b2s;
        #pragma unroll
        for (int nt = 0; nt < 2; nt++)
            #pragma unroll
            for (int i = 0; i < 2; i++) sc[nt][i] += b2v;

        // softmax over the warp's 16 rows (4 per lane, duplicated over g)
        float m = fmaxf(fmaxf(sc[0][0], sc[0][1]), fmaxf(sc[1][0], sc[1][1]));
        m = fmaxf(m, __shfl_xor_sync(0xffffffffu, m, 1));
        m = fmaxf(m, __shfl_xor_sync(0xffffffffu, m, 2));
        float e[2][2], esum = 0.f;
        #pragma unroll
        for (int nt = 0; nt < 2; nt++)
            #pragma unroll
            for (int i = 0; i < 2; i++) { e[nt][i] = __expf(sc[nt][i] - m); esum += e[nt][i]; }
        esum += __shfl_xor_sync(0xffffffffu, esum, 1);
        esum += __shfl_xor_sync(0xffffffffu, esum, 2);
        const float inv = 1.0f / esum;

        if (g == 0) {
            #pragma unroll
            for (int nt = 0; nt < 2; nt++)
                #pragma unroll
                for (int i = 0; i < 2; i++)
                    out[rbase + wid * 16 + nt * 8 + 2 * c + i] = e[nt][i] * inv;
        }
    }
}

extern "C" void kernel_launch(void* const* d_in, const int* in_sizes, int n_in,
                              void* d_out, int out_size) {
    const float* dyn   = (const float*)d_in[0];
    const float* stat  = (const float*)d_in[1];
    const float* gamma = (const float*)d_in[2];
    const float* beta  = (const float*)d_in[3];
    const float* w1    = (const float*)d_in[4];
    const float* b1    = (const float*)d_in[5];
    const float* w2    = (const float*)d_in[6];
    const float* b2    = (const float*)d_in[7];
    float* out = (float*)d_out;

    const long nrows = (long)in_sizes[0] / 16;      // 4,194,304
    const long tiles = nrows / TILE_M;              // 32,768
    const int  tpb   = (int)(tiles / GRID_B);       // 16

    prep_kernel<<<1, 64>>>(gamma, beta, w1, b1, w2, b2);
    dwa_kernel<<<GRID_B, 256>>>(dyn, stat, out, tpb);
}

// round 10
// speedup vs baseline: 2.5105x; 1.1022x over previous
#include <cuda_runtime.h>
#include <cstdint>

// DynamicWeightAttention via mma.sync tf32, double-buffered, k-reordered smem,
// A-fragments in SMEM (frees ~48 regs) -> occupancy 3 (24 warps/SM).
// D^T[64,M] = W'^T[64,32] x X^T[32,M]; LN folded into epilogue; softmax over 16.

#define C_FEAT 32
#define HID    64
#define TILE_M 128
#define GRID_B 2048
#define XROW   36                 // padded words per row
#define XBUF   (TILE_M * XROW)    // words per buffer

// ---- prep outputs (device globals; no allocation) ----
__device__ float  g_W[HID * C_FEAT];  // [d][k] = tf32(gamma[k]*w1[k][d])
__device__ float4 g_p4[HID];          // {u_d, v_d, w2_d, 0}
__device__ float  g_b2;

__device__ __forceinline__ uint32_t tf32r(float x) {
    uint32_t r; asm("cvt.rna.tf32.f32 %0, %1;" : "=r"(r) : "f"(x)); return r;
}
__device__ __forceinline__ float tanha(float x) {
    float r; asm("tanh.approx.f32 %0, %1;" : "=f"(r) : "f"(x)); return r;
}
__device__ __forceinline__ void mma8(float& d0, float& d1, float& d2, float& d3,
                                     uint32_t a0, uint32_t a1, uint32_t a2, uint32_t a3,
                                     uint32_t b0, uint32_t b1) {
    asm("mma.sync.aligned.m16n8k8.row.col.f32.tf32.tf32.f32 "
        "{%0,%1,%2,%3}, {%4,%5,%6,%7}, {%8,%9}, {%0,%1,%2,%3};"
        : "+f"(d0), "+f"(d1), "+f"(d2), "+f"(d3)
        : "r"(a0), "r"(a1), "r"(a2), "r"(a3), "r"(b0), "r"(b1));
}

__global__ void prep_kernel(const float* __restrict__ gamma, const float* __restrict__ beta,
                            const float* __restrict__ w1,    const float* __restrict__ b1,
                            const float* __restrict__ w2,    const float* __restrict__ b2) {
    int d = threadIdx.x;
    if (d >= HID) return;
    float u = 0.f, v = 0.f;
    for (int k = 0; k < C_FEAT; k++) {
        float wp = __uint_as_float(tf32r(gamma[k] * w1[k * HID + d]));
        g_W[d * C_FEAT + k] = wp;
        u += wp;
        v += beta[k] * w1[k * HID + d];
    }
    g_p4[d] = make_float4(u, v + b1[d], w2[d], 0.f);
    if (d == 0) g_b2 = b2[0];
}

__global__ __launch_bounds__(256, 3)
void dwa_kernel(const float* __restrict__ dyn, const float* __restrict__ stat,
                float* __restrict__ out, int tiles_per_block) {
    __shared__ uint32_t xs[2 * XBUF];                 // 36 KB (double buffer)
    __shared__ __align__(16) uint4  aw[16][32];       // 8 KB: A-frag per (mt*4+ks, lane)
    __shared__ __align__(16) float4 p4s[HID];         // 1 KB
    __shared__ float b2s;

    const int tid  = threadIdx.x;
    const int lane = tid & 31;
    const int wid  = tid >> 5;
    const int g    = lane >> 2;     // groupID
    const int c    = lane & 3;      // threadID_in_group
    const int lrow = tid >> 1;      // local row this thread stages (0..127)
    const int half = tid & 1;       // 8-col slice of dyn AND of stat

    if (tid < HID) p4s[tid] = g_p4[tid];
    if (tid == 0)  b2s = g_b2;

    // ---- build A-fragment table in smem (once per block) ----
    // slab s = mt*4+ks, lane l=(g,c): {W[16mt+g][8ks+c], W[+8][..], W[..][+4], W[+8][+4]}
    for (int e = tid; e < 512; e += 256) {
        int sI = e >> 5, l = e & 31;
        int mt = sI >> 2, ks = sI & 3;
        int gg = l >> 2, cc = l & 3;
        int d0 = mt * 16 + gg, k0 = ks * 8 + cc;
        uint4 v;
        v.x = __float_as_uint(g_W[d0 * 32 + k0]);
        v.y = __float_as_uint(g_W[(d0 + 8) * 32 + k0]);
        v.z = __float_as_uint(g_W[d0 * 32 + k0 + 4]);
        v.w = __float_as_uint(g_W[(d0 + 8) * 32 + k0 + 4]);
        aw[sI][l] = v;
    }
    __syncthreads();   // aw/p4s/b2s visible

    for (int it = 0; it < tiles_per_block; it++) {
        const long tile  = (long)blockIdx.x * tiles_per_block + it;
        const long rbase = tile * TILE_M;
        const long row   = rbase + lrow;
        uint32_t* xb = xs + (it & 1) * XBUF;

        // ---- stage half a row into registers (before the barrier) ----
        uint32_t xw[16];
        float s = 0.f, ss = 0.f;
        {
            const float4* d4 = (const float4*)dyn + row * 4 + half * 2;
            const float4* s4 = (const float4*)stat + (long)(row & 4095) * 4 + half * 2;
            #pragma unroll
            for (int k = 0; k < 2; k++) {
                float4 v = d4[k];
                s += v.x + v.y + v.z + v.w;
                ss += v.x*v.x + v.y*v.y + v.z*v.z + v.w*v.w;
                xw[4*k] = tf32r(v.x); xw[4*k+1] = tf32r(v.y);
                xw[4*k+2] = tf32r(v.z); xw[4*k+3] = tf32r(v.w);
            }
            #pragma unroll
            for (int k = 0; k < 2; k++) {
                float4 v = s4[k];
                s += v.x + v.y + v.z + v.w;
                ss += v.x*v.x + v.y*v.y + v.z*v.z + v.w*v.w;
                xw[8+4*k] = tf32r(v.x); xw[8+4*k+1] = tf32r(v.y);
                xw[8+4*k+2] = tf32r(v.z); xw[8+4*k+3] = tf32r(v.w);
            }
        }
        s  += __shfl_xor_sync(0xffffffffu, s, 1);
        ss += __shfl_xor_sync(0xffffffffu, ss, 1);
        const float mean = s * (1.0f / C_FEAT);
        const float var  = ss * (1.0f / C_FEAT) - mean * mean;
        const float rstd = rsqrtf(var + 1e-4f);

        // ---- k-reordered stores: word k -> p = (k&3)*8 + (k>>3)*2 + ((k>>2)&1)
        {
            uint32_t* xr = xb + lrow * XROW;
            #pragma unroll
            for (int j = 0; j < 4; j++) {
                *(uint2*)(xr + j * 8 + 2 * half)     = make_uint2(xw[j],     xw[j + 4]);
                *(uint2*)(xr + j * 8 + 4 + 2 * half) = make_uint2(xw[8 + j], xw[12 + j]);
            }
        }
        __syncthreads();   // single barrier per tile (double buffer)

        // ---- b fragments: 2x LDS.128 per nt-row ----
        uint4 blo[2], bhi[2];
        #pragma unroll
        for (int nt = 0; nt < 2; nt++) {
            int brow = wid * 16 + nt * 8 + g;
            const uint4* q = (const uint4*)(xb + brow * XROW + c * 8);
            blo[nt] = q[0]; bhi[nt] = q[1];
        }

        float acc[4][2][4];
        #pragma unroll
        for (int mt = 0; mt < 4; mt++)
            #pragma unroll
            for (int nt = 0; nt < 2; nt++)
                #pragma unroll
                for (int q = 0; q < 4; q++) acc[mt][nt][q] = 0.f;

        #pragma unroll
        for (int ks = 0; ks < 4; ks++) {
            uint4 a[4];
            #pragma unroll
            for (int mt = 0; mt < 4; mt++) a[mt] = aw[mt * 4 + ks][lane];
            uint32_t b0[2], b1[2];
            #pragma unroll
            for (int nt = 0; nt < 2; nt++) {
                b0[nt] = (ks == 0) ? blo[nt].x : (ks == 1) ? blo[nt].z
                        : (ks == 2) ? bhi[nt].x : bhi[nt].z;
                b1[nt] = (ks == 0) ? blo[nt].y : (ks == 1) ? blo[nt].w
                        : (ks == 2) ? bhi[nt].y : bhi[nt].w;
            }
            #pragma unroll
            for (int mt = 0; mt < 4; mt++)
                #pragma unroll
                for (int nt = 0; nt < 2; nt++)
                    mma8(acc[mt][nt][0], acc[mt][nt][1], acc[mt][nt][2], acc[mt][nt][3],
                         a[mt].x, a[mt].y, a[mt].z, a[mt].w, b0[nt], b1[nt]);
        }

        // ---- epilogue: thread holds d in {16mt+g, +8}, rows {8nt+2c, +1} ----
        float sc[2][2], mrow[2][2], rrow[2][2];
        #pragma unroll
        for (int nt = 0; nt < 2; nt++)
            #pragma unroll
            for (int i = 0; i < 2; i++) {
                int src = (nt * 8 + 2 * c + i) * 2;
                mrow[nt][i] = __shfl_sync(0xffffffffu, mean, src);
                rrow[nt][i] = __shfl_sync(0xffffffffu, rstd, src);
                sc[nt][i] = 0.f;
            }
        #pragma unroll
        for (int mt = 0; mt < 4; mt++) {
            #pragma unroll
            for (int hh = 0; hh < 2; hh++) {
                int d = mt * 16 + g + 8 * hh;
                float4 p = p4s[d];          // {u, v, w2}
                #pragma unroll
                for (int nt = 0; nt < 2; nt++) {
                    #pragma unroll
                    for (int i = 0; i < 2; i++) {
                        float t1 = fmaf(-mrow[nt][i], p.x, acc[mt][nt][2*hh + i]);
                        float h  = fmaf(t1, rrow[nt][i], p.y);
                        sc[nt][i] = fmaf(tanha(h), p.z, sc[nt][i]);
                    }
                }
            }
        }
        // reduce partial scores over g-lanes (offsets 4,8,16 preserve c)
        #pragma unroll
        for (int o = 4; o <= 16; o <<= 1) {
            #pragma unroll
            for (int nt = 0; nt < 2; nt++)
                #pragma unroll
                for (int i = 0; i < 2; i++)
                    sc[nt][i] += __shfl_xor_sync(0xffffffffu, sc[nt][i], o);
        }
        const float b2v = b2s;
        #pragma unroll
        for (int nt = 0; nt < 2; nt++)
            #pragma unroll
            for (int i = 0; i < 2; i++) sc[nt][i] += b2v;

        // softmax over the warp's 16 rows (4 per lane, duplicated over g)
        float m = fmaxf(fmaxf(sc[0][0], sc[0][1]), fmaxf(sc[1][0], sc[1][1]));
        m = fmaxf(m, __shfl_xor_sync(0xffffffffu, m, 1));
        m = fmaxf(m, __shfl_xor_sync(0xffffffffu, m, 2));
        float e[2][2], esum = 0.f;
        #pragma unroll
        for (int nt = 0; nt < 2; nt++)
            #pragma unroll
            for (int i = 0; i < 2; i++) { e[nt][i] = __expf(sc[nt][i] - m); esum += e[nt][i]; }
        esum += __shfl_xor_sync(0xffffffffu, esum, 1);
        esum += __shfl_xor_sync(0xffffffffu, esum, 2);
        const float inv = 1.0f / esum;

        if (g == 0) {
            #pragma unroll
            for (int nt = 0; nt < 2; nt++)
                #pragma unroll
                for (int i = 0; i < 2; i++)
                    out[rbase + wid * 16 + nt * 8 + 2 * c + i] = e[nt][i] * inv;
        }
    }
}

extern "C" void kernel_launch(void* const* d_in, const int* in_sizes, int n_in,
                              void* d_out, int out_size) {
    const float* dyn   = (const float*)d_in[0];
    const float* stat  = (const float*)d_in[1];
    const float* gamma = (const float*)d_in[2];
    const float* beta  = (const float*)d_in[3];
    const float* w1    = (const float*)d_in[4];
    const float* b1    = (const float*)d_in[5];
    const float* w2    = (const float*)d_in[6];
    const float* b2    = (const float*)d_in[7];
    float* out = (float*)d_out;

    const long nrows = (long)in_sizes[0] / 16;      // 4,194,304
    const long tiles = nrows / TILE_M;              // 32,768
    const int  tpb   = (int)(tiles / GRID_B);       // 16

    prep_kernel<<<1, 64>>>(gamma, beta, w1, b1, w2, b2);
    dwa_kernel<<<GRID_B, 256>>>(dyn, stat, out, tpb);
}